// round 17
// baseline (speedup 1.0000x reference)
#include <cuda_runtime.h>
#include <cuda_bf16.h>

#define BB   64
#define DPT  128
#define HW   121
#define OCH  16
#define FEAT_SZ (OCH*HW)

typedef unsigned long long u64;
typedef unsigned int u32;
union F2U { u64 u; float2 f; };

__device__ __forceinline__ u64 fma2(u64 a, u64 b, u64 c) {
    u64 d; asm("fma.rn.f32x2 %0, %1, %2, %3;" : "=l"(d) : "l"(a), "l"(b), "l"(c)); return d;
}
__device__ __forceinline__ u64 dup2(float w) {
    u64 d; asm("mov.b64 %0, {%1, %1};" : "=l"(d) : "f"(w)); return d;
}
__device__ __forceinline__ void mma_bf16(float (&c)[4], u32 a0, u32 a1, u32 a2, u32 a3,
                                         u32 b0, u32 b1) {
    asm volatile("mma.sync.aligned.m16n8k16.row.col.f32.bf16.bf16.f32 "
        "{%0,%1,%2,%3}, {%4,%5,%6,%7}, {%8,%9}, {%0,%1,%2,%3};"
        : "+f"(c[0]), "+f"(c[1]), "+f"(c[2]), "+f"(c[3])
        : "r"(a0), "r"(a1), "r"(a2), "r"(a3), "r"(b0), "r"(b1));
}
__device__ __forceinline__ u32 pack_bf16(__nv_bfloat16 lo, __nv_bfloat16 hi) {
    __nv_bfloat162 t = __nv_bfloat162(lo, hi);
    return *reinterpret_cast<u32*>(&t);
}

__device__ float g_sa1[BB*OCH*DPT*HW];
__device__ float g_sa2[BB*OCH*DPT*HW];
__device__ float g_feat[5*BB*OCH*HW];
__device__ float g_alpha[3*OCH*DPT];
__device__ u32   g_wsplit[2*16128];   // per layer: [kk63][o16][q4][hi_h0,hi_h1,lo_h0,lo_h1]

// ---------------------------------------------------------------------------
// prep: alpha softmax (0..47), weight split interleaved hi/lo (48..111),
// zero out (112..115), zero feat (116..).
// ---------------------------------------------------------------------------
__global__ void prep_kernel(const float* __restrict__ cw, const float* __restrict__ w3d23,
                            float* __restrict__ alpha, u32* __restrict__ wsp,
                            float* __restrict__ out, int out_n, float* __restrict__ feat)
{
    const int bid = blockIdx.x, tid = threadIdx.x;
    if (bid < 48) {
        __shared__ float red[128];
        float wv = 0.f, e = 0.f;
        if (tid < 128) { wv = cw[bid*128 + tid]; red[tid] = wv; }
        __syncthreads();
        for (int s = 64; s > 0; s >>= 1) { if (tid < s) red[tid] = fmaxf(red[tid], red[tid+s]); __syncthreads(); }
        float mx = red[0]; __syncthreads();
        if (tid < 128) { e = expf(wv - mx); red[tid] = e; }
        __syncthreads();
        for (int s = 64; s > 0; s >>= 1) { if (tid < s) red[tid] += red[tid+s]; __syncthreads(); }
        if (tid < 128) alpha[bid*128 + tid] = e / red[0];
    } else if (bid < 112) {
        int g = (bid - 48)*256 + tid;
        if (g < 16128) {
            int layer = g / 8064, tt = g - layer*8064;
            int kk = tt >> 7, r = tt & 127;
            int o = r >> 3, s2 = r & 7;
            int q = s2 >> 1, half = s2 & 1;
            const float* wt = w3d23 + layer*16128;
            int c0 = 2*q + 8*half;
            float x0 = wt[o*1008 + c0*63 + kk];
            float x1 = wt[o*1008 + (c0+1)*63 + kk];
            __nv_bfloat16 h0 = __float2bfloat16(x0);
            __nv_bfloat16 h1 = __float2bfloat16(x1);
            __nv_bfloat16 l0 = __float2bfloat16(x0 - __bfloat162float(h0));
            __nv_bfloat16 l1 = __float2bfloat16(x1 - __bfloat162float(h1));
            u32* dst = wsp + layer*16128;
            int base = kk*256 + o*16 + q*4 + half;   // u32 units
            dst[base]     = pack_bf16(h0, h1);
            dst[base + 2] = pack_bf16(l0, l1);
        }
    } else if (bid < 116) {
        int g = (bid - 112)*256 + tid;
        if (g < out_n) out[g] = 0.f;
    } else {
        int g = (bid - 116)*256 + tid;
        if (g < 3*BB*FEAT_SZ) feat[g] = 0.f;
    }
}

// ---------------------------------------------------------------------------
// Layer-1 scalar conv (ICH=1), packed f32x2, fused cpr partials
// ---------------------------------------------------------------------------
__global__ void __launch_bounds__(256, 2) conv3d1_kernel(
    const float* __restrict__ in, const float* __restrict__ wt,
    const float* __restrict__ bias, float* __restrict__ out,
    const float* __restrict__ alpha, float* __restrict__ featL)
{
    const int d0 = blockIdx.x * 8;
    const int b  = blockIdx.y;
    extern __shared__ float sm[];
    float*  w_s = sm;
    float2* in2 = (float2*)(sm + 63*16);
    __shared__ float alpha_s[128];
    const int tid = threadIdx.x;
    if (tid < 128) alpha_s[tid] = alpha[(tid >> 3)*128 + d0 + (tid & 7)];

    const int og = tid >> 7, pos = tid & 127;
    const int cpos = pos < HW ? pos : HW-1;
    const int h = cpos / 11, w = cpos - h*11;
    const int ppc = (h+1)*13 + (w+1);

    u64 acc[4][8];
    #pragma unroll
    for (int r = 0; r < 4; r++)
        #pragma unroll
        for (int o = 0; o < 8; o++) acc[r][o] = 0ULL;

    for (int t = tid; t < OCH*63; t += 256) { int o = t/63, r = t - o*63; w_s[r*16 + o] = wt[o*63 + r]; }
    for (int t = tid; t < 13*169; t += 256) {
        int dd = t/169, pp = t - dd*169;
        int h13 = pp/13, w13 = pp - h13*13, gd = d0 - 3 + dd;
        float v0 = 0.f, v1 = 0.f;
        if (h13 >= 1 && h13 <= 11 && w13 >= 1 && w13 <= 11) {
            const float* src = in + (size_t)b*DPT*HW + (h13-1)*11 + (w13-1);
            if (gd   >= 0 && gd   < DPT) v0 = src[(size_t)gd*HW];
            if (gd+1 >= 0 && gd+1 < DPT) v1 = src[(size_t)(gd+1)*HW];
        }
        in2[t] = make_float2(v0, v1);
    }
    __syncthreads();

    const u64*   col = (const u64*)in2 + ppc;
    const float* wb  = w_s + og*8;
    #pragma unroll 1
    for (int kd = 0; kd < 7; ++kd) {
        #pragma unroll
        for (int khw = 0; khw < 9; ++khw) {
            const int kh = khw/3, kw = khw - kh*3;
            const int off = (kh-1)*13 + (kw-1);
            const float* wk = wb + (kd*9 + khw)*16;
            float4 wa = *reinterpret_cast<const float4*>(wk);
            float4 wc = *reinterpret_cast<const float4*>(wk + 4);
            u64 wd[8] = {dup2(wa.x), dup2(wa.y), dup2(wa.z), dup2(wa.w),
                         dup2(wc.x), dup2(wc.y), dup2(wc.z), dup2(wc.w)};
            #pragma unroll
            for (int r = 0; r < 4; ++r) {
                u64 a = col[(kd + 2*r)*169 + off];
                #pragma unroll
                for (int o = 0; o < 8; ++o) acc[r][o] = fma2(a, wd[o], acc[r][o]);
            }
        }
    }

    if (pos < HW) {
        #pragma unroll
        for (int o = 0; o < 8; ++o) {
            const int oc = og*8 + o;
            const float bv = bias[oc];
            float* ob = out + ((size_t)(b*OCH + oc)*DPT + d0)*HW + pos;
            float fs = 0.f;
            #pragma unroll
            for (int r = 0; r < 4; ++r) {
                F2U a; a.u = acc[r][o];
                float v0 = fmaxf(a.f.x + bv, 0.f), v1 = fmaxf(a.f.y + bv, 0.f);
                ob[(2*r  )*HW] = v0;
                ob[(2*r+1)*HW] = v1;
                fs += alpha_s[oc*8 + 2*r]*v0 + alpha_s[oc*8 + 2*r + 1]*v1;
            }
            atomicAdd(&featL[b*FEAT_SZ + oc*HW + pos], fs);
        }
    }
}

// ---------------------------------------------------------------------------
// Layers 2/3: HMMA, merged 3-product kk loop, hi/lo INTERLEAVED 16B-adjacent:
// every operand fragment (hi+lo) = ONE LDS.128. Per kk/warp: 2 A + 8 B LDS.128
// + 24 mma (was 20 LDS.64). Epilogue: smem partials + 1936 atomics per CTA.
// X row per (dep,pp) = 64B: q*16 + half*4 (hi), +8 (lo). W row per kk = 1024B.
// ---------------------------------------------------------------------------
#define DEPS   10816               // 169*64
#define WOFFB  151424              // 14*10816
#define SMEM_CT (WOFFB + 64512)    // + 63*1024 = 215936

template<bool WRITE_SA>
__global__ void __launch_bounds__(512, 1) convT2_kernel(
    const float* __restrict__ in, const u32* __restrict__ wsp,
    const float* __restrict__ bias, float* __restrict__ out,
    const float* __restrict__ alpha, float* __restrict__ featL)
{
    extern __shared__ char smx[];
    const int d0 = blockIdx.x * 8;
    const int b  = blockIdx.y;
    const int tid = threadIdx.x, wid = tid >> 5, l = tid & 31;

    {
        u32* wdst = (u32*)(smx + WOFFB);
        for (int t = tid; t < 16128; t += 512) wdst[t] = wsp[t];
    }
    // X slab: addr = dep*DEPS + pp*64 + q*16 + half*4 (hi), +8 (lo)
    for (int t = tid; t < 8*14*169; t += 512) {
        int iq  = t / (14*169);
        int r   = t - iq*(14*169);
        int dep = r / 169, pp = r - dep*169;
        int q = iq >> 1, half = iq & 1;
        int gd  = d0 - 3 + dep;
        int h13 = pp / 13, w13 = pp - h13*13;
        float x0 = 0.f, x1 = 0.f;
        if (gd >= 0 && gd < DPT && h13 >= 1 && h13 <= 11 && w13 >= 1 && w13 <= 11) {
            int c0 = 2*q + 8*half;
            const float* src = in + ((size_t)(b*OCH + c0)*DPT + gd)*HW + (h13-1)*11 + (w13-1);
            x0 = src[0];
            x1 = src[(size_t)DPT*HW];
        }
        __nv_bfloat16 h0 = __float2bfloat16(x0);
        __nv_bfloat16 h1 = __float2bfloat16(x1);
        __nv_bfloat16 l0 = __float2bfloat16(x0 - __bfloat162float(h0));
        __nv_bfloat16 l1 = __float2bfloat16(x1 - __bfloat162float(h1));
        int addr = dep*DEPS + pp*64 + q*16 + half*4;
        *(u32*)(smx + addr)     = pack_bf16(h0, h1);
        *(u32*)(smx + addr + 8) = pack_bf16(l0, l1);
    }
    __syncthreads();

    int coff[8];
    #pragma unroll
    for (int k = 0; k < 8; ++k) {
        int T = wid + 16*k;
        int Tc = T < 121 ? T : 120;
        int n  = Tc*8 + (l >> 2);
        int dl = n / 121, p = n - dl*121;
        int pp = (p/11 + 1)*13 + (p%11) + 1;
        coff[k] = dl*DEPS + pp*64 + (l & 3)*16;
    }
    const int aoff = (l >> 2)*64 + (l & 3)*16;

    float acc[8][4];
    #pragma unroll
    for (int k = 0; k < 8; ++k)
        #pragma unroll
        for (int q = 0; q < 4; ++q) acc[k][q] = 0.f;

    const bool last_ok = (wid < 9);
    #pragma unroll 1
    for (int kk = 0; kk < 63; ++kk) {
        const char* Wk = smx + WOFFB + kk*1024;
        ulonglong2 w0 = *(const ulonglong2*)(Wk + aoff);         // row o0: (hi h02, lo l02)
        ulonglong2 w1 = *(const ulonglong2*)(Wk + aoff + 512);   // row o0+8
        u32 ah0 = (u32)w0.x, ah2 = (u32)(w0.x >> 32);
        u32 al0 = (u32)w0.y, al2 = (u32)(w0.y >> 32);
        u32 ah1 = (u32)w1.x, ah3 = (u32)(w1.x >> 32);
        u32 al1 = (u32)w1.y, al3 = (u32)(w1.y >> 32);
        int kd = kk / 9, khw = kk - kd*9;
        int kh = khw / 3, kw = khw - kh*3;
        const char* Xk = smx + kd*DEPS + ((kh-1)*13 + (kw-1))*64;
        // batch all B loads (hi+lo in one LDS.128 each), then all mmas
        ulonglong2 bb[8];
        #pragma unroll
        for (int k = 0; k < 8; ++k) {
            if (k < 7 || last_ok)
                bb[k] = *(const ulonglong2*)(Xk + coff[k]);
        }
        #pragma unroll
        for (int k = 0; k < 8; ++k) {
            if (k < 7 || last_ok) {
                u32 bh0 = (u32)bb[k].x, bh1 = (u32)(bb[k].x >> 32);
                u32 bl0 = (u32)bb[k].y, bl1 = (u32)(bb[k].y >> 32);
                mma_bf16(acc[k], ah0, ah1, ah2, ah3, bh0, bh1);
                mma_bf16(acc[k], al0, al1, al2, al3, bh0, bh1);
                mma_bf16(acc[k], ah0, ah1, ah2, ah3, bl0, bl1);
            }
        }
    }

    __syncthreads();   // mma done; reuse X slab as pbuf[8 dl][16 o][121 p]
    float* pbuf = (float*)smx;

    const int o0 = l >> 2, o1 = o0 + 8;
    const float bv0 = bias[o0], bv1 = bias[o1];
    #pragma unroll 1
    for (int k = 0; k < 8; ++k) {
        if (k < 7 || last_ok) {
            int T = wid + 16*k;
            #pragma unroll
            for (int cc = 0; cc < 2; ++cc) {
                int nn = T*8 + (l & 3)*2 + cc;
                int dl = nn / 121, p = nn - dl*121;
                int gdo = d0 + dl;
                float v0 = fmaxf(acc[k][cc    ] + bv0, 0.f);
                float v1 = fmaxf(acc[k][cc + 2] + bv1, 0.f);
                if (WRITE_SA) {
                    out[((size_t)(b*OCH + o0)*DPT + gdo)*HW + p] = v0;
                    out[((size_t)(b*OCH + o1)*DPT + gdo)*HW + p] = v1;
                }
                pbuf[(dl*16 + o0)*121 + p] = alpha[o0*128 + gdo]*v0;
                pbuf[(dl*16 + o1)*121 + p] = alpha[o1*128 + gdo]*v1;
            }
        }
    }
    __syncthreads();
    for (int t = tid; t < FEAT_SZ; t += 512) {
        int o = t / 121, p = t - o*121;
        float s = 0.f;
        #pragma unroll
        for (int dl = 0; dl < 8; ++dl) s += pbuf[(dl*16 + o)*121 + p];
        atomicAdd(&featL[b*FEAT_SZ + t], s);
    }
}

// ---------------------------------------------------------------------------
__global__ void relu_kernel(float* x, int n)
{
    int t = blockIdx.x*blockDim.x + threadIdx.x;
    if (t < n) x[t] = fmaxf(x[t], 0.f);
}

// conv4/conv5 2D, 512 threads: og = tid>>7 handles 4 o each, pos = tid&127.
__global__ void __launch_bounds__(512) conv45_kernel(
    const float* __restrict__ feat2,
    const float* __restrict__ w45, const float* __restrict__ b45,
    float* __restrict__ feat3, float* __restrict__ feat4)
{
    const int b = blockIdx.x, tid = threadIdx.x;
    const int og = tid >> 7, pos = tid & 127;
    __shared__ float fa[FEAT_SZ], fb[FEAT_SZ];
    for (int t = tid; t < FEAT_SZ; t += 512) fa[t] = feat2[b*FEAT_SZ + t];
    __syncthreads();
    if (pos < HW) {
        int h = pos / 11, w = pos - h*11;
        for (int oo = 0; oo < 4; oo++) {
            int o = og*4 + oo;
            float acc = b45[o];
            for (int c = 0; c < 16; c++)
                #pragma unroll
                for (int kh = 0; kh < 3; kh++) {
                    int hh = h + kh - 1; if (hh < 0 || hh >= 11) continue;
                    #pragma unroll
                    for (int kw = 0; kw < 3; kw++) {
                        int ww2 = w + kw - 1; if (ww2 < 0 || ww2 >= 11) continue;
                        acc += fa[c*HW + hh*11 + ww2] * w45[(o*16 + c)*9 + kh*3 + kw];
                    }
                }
            float v = fmaxf(acc, 0.f);
            fb[o*HW + pos] = v;
            feat3[b*FEAT_SZ + o*HW + pos] = v;
        }
    }
    __syncthreads();
    if (pos < HW) {
        int h = pos / 11, w = pos - h*11;
        for (int oo = 0; oo < 4; oo++) {
            int o = og*4 + oo;
            float acc = b45[16 + o];
            for (int c = 0; c < 16; c++)
                #pragma unroll
                for (int kh = 0; kh < 3; kh++) {
                    int hh = h + kh - 1; if (hh < 0 || hh >= 11) continue;
                    #pragma unroll
                    for (int kw = 0; kw < 3; kw++) {
                        int ww2 = w + kw - 1; if (ww2 < 0 || ww2 >= 11) continue;
                        acc += fb[c*HW + hh*11 + ww2] * w45[2304 + (o*16 + c)*9 + kh*3 + kw];
                    }
                }
            feat4[b*FEAT_SZ + o*HW + pos] = fmaxf(acc, 0.f);
        }
    }
}

__global__ void side_kernel(const float* __restrict__ x, const float* __restrict__ feat,
    const float* __restrict__ sw,  const float* __restrict__ sb,
    const float* __restrict__ sow, const float* __restrict__ sob,
    const float* __restrict__ wa,  const float* __restrict__ ba,
    const float* __restrict__ wb,  const float* __restrict__ bbv,
    const float* __restrict__ ssw, const float* __restrict__ ssb,
    const float* __restrict__ fuse, float* __restrict__ out)
{
    const int i = blockIdx.x, b = blockIdx.y, tid = threadIdx.x;
    __shared__ float f_s[FEAT_SZ], act_s[HW], diff_s[HW], s_arr[128], xc[128], y1_s[144], y2_s[16];
    __shared__ int idx_s[5];

    for (int t = tid; t < FEAT_SZ; t += 128)
        f_s[t] = feat[i*(BB*FEAT_SZ) + b*FEAT_SZ + t];
    __syncthreads();

    if (tid < HW) {
        int h = tid / 11, w = tid - h*11;
        float acc = sb[i];
        for (int c = 0; c < 16; c++)
            for (int kh = 0; kh < 3; kh++) {
                int hh = h + kh - 1; if (hh < 0 || hh >= 11) continue;
                for (int kw = 0; kw < 3; kw++) {
                    int ww2 = w + kw - 1; if (ww2 < 0 || ww2 >= 11) continue;
                    acc += f_s[c*HW + hh*11 + ww2] * sw[(i*16 + c)*9 + kh*3 + kw];
                }
            }
        act_s[tid] = acc;
    }
    __syncthreads();
    if (tid < HW) diff_s[tid] = fabsf(act_s[tid] - act_s[60]);
    __syncthreads();
    if (tid == 0) {
        for (int j = 0; j < 5; j++) {
            float best = 3.4e38f; int bi = 0;
            for (int p = 0; p < HW; p++) { float d = diff_s[p]; if (d < best) { best = d; bi = p; } }
            idx_s[j] = bi; diff_s[bi] = 3.4e38f;
        }
    }
    __syncthreads();
    {
        float s = 0.f;
        const float* xb = x + (size_t)(b*128 + tid)*HW;
        #pragma unroll
        for (int j = 0; j < 5; j++) s += xb[idx_s[j]];
        s_arr[tid] = s;
        xc[tid] = xb[60];
    }
    __syncthreads();
    for (int t = tid; t < 144; t += 128) {
        int o = t / 9, j = t - o*9;
        int pj = 62 + 2*(j/3), qj = 62 + 2*(j%3);
        float acc = ba[i*16 + o];
        #pragma unroll
        for (int ch = 0; ch < 2; ch++) {
            const float* num = ch ? xc : s_arr;
            #pragma unroll
            for (int eh = 0; eh < 3; eh++)
                #pragma unroll
                for (int ew = 0; ew < 3; ew++) {
                    int r = pj + eh - 1, c = qj + ew - 1;
                    float den = num[c];
                    den = fabsf(den) < 0.01f ? 0.01f : den;
                    acc += (num[r] / den) * wa[(((i*16 + o)*2 + ch)*3 + eh)*3 + ew];
                }
        }
        y1_s[o*9 + j] = fmaxf(acc, 0.f);
    }
    __syncthreads();
    if (tid < 16) {
        float acc = bbv[i*16 + tid];
        for (int c = 0; c < 16; c++)
            #pragma unroll
            for (int j = 0; j < 9; j++)
                acc += y1_s[c*9 + j] * wb[((i*16 + tid)*16 + c)*9 + j];
        y2_s[tid] = fmaxf(acc, 0.f);
    }
    __syncthreads();
    if (tid < 16) {
        float sa_v = sob[i*16 + tid];
        for (int k = 0; k < 16; k++) sa_v += f_s[k*HW + 60] * sow[(i*16 + tid)*16 + k];
        float sp_v = ssb[i*16 + tid];
        for (int c = 0; c < 16; c++) sp_v += y2_s[c] * ssw[(i*16 + tid)*16 + c];
        atomicAdd(&out[b*16 + tid], fuse[i]*sa_v + fuse[5 + i]*sp_v);
    }
}

// ---------------------------------------------------------------------------
extern "C" void kernel_launch(void* const* d_in, const int* in_sizes, int n_in,
                              void* d_out, int out_size)
{
    const float* x      = (const float*)d_in[0];
    const float* w3d1   = (const float*)d_in[1];
    const float* b3d1   = (const float*)d_in[2];
    const float* w3d23  = (const float*)d_in[3];
    const float* b3d23  = (const float*)d_in[4];
    const float* cpr_w  = (const float*)d_in[5];
    const float* w2d45  = (const float*)d_in[6];
    const float* b2d45  = (const float*)d_in[7];
    const float* seg_w  = (const float*)d_in[8];
    const float* seg_b  = (const float*)d_in[9];
    const float* so_w   = (const float*)d_in[10];
    const float* so_b   = (const float*)d_in[11];
    const float* sp_wa  = (const float*)d_in[12];
    const float* sp_ba  = (const float*)d_in[13];
    const float* sp_wb  = (const float*)d_in[14];
    const float* sp_bb  = (const float*)d_in[15];
    const float* sp_sw  = (const float*)d_in[16];
    const float* sp_sb  = (const float*)d_in[17];
    const float* fuse   = (const float*)d_in[18];
    float* out = (float*)d_out;

    float *sa1, *sa2, *feat, *alpha;
    u32* wsp;
    cudaGetSymbolAddress((void**)&sa1,   g_sa1);
    cudaGetSymbolAddress((void**)&sa2,   g_sa2);
    cudaGetSymbolAddress((void**)&feat,  g_feat);
    cudaGetSymbolAddress((void**)&alpha, g_alpha);
    cudaGetSymbolAddress((void**)&wsp,   g_wsplit);

    const int SMEM1 = 63*16*4 + 13*169*8;
    cudaFuncSetAttribute((const void*)conv3d1_kernel, cudaFuncAttributeMaxDynamicSharedMemorySize, SMEM1);
    cudaFuncSetAttribute((const void*)convT2_kernel<true>,  cudaFuncAttributeMaxDynamicSharedMemorySize, SMEM_CT);
    cudaFuncSetAttribute((const void*)convT2_kernel<false>, cudaFuncAttributeMaxDynamicSharedMemorySize, SMEM_CT);

    const int prep_blocks = 116 + (3*BB*FEAT_SZ + 255)/256;
    prep_kernel<<<prep_blocks, 256>>>(cpr_w, w3d23, alpha, wsp, out, out_size, feat);

    conv3d1_kernel<<<dim3(16, BB), 256, SMEM1>>>(
        x, w3d1, b3d1, sa1, alpha + 0*2048, feat + 0*(BB*FEAT_SZ));

    convT2_kernel<true><<<dim3(16, BB), 512, SMEM_CT>>>(
        sa1, wsp, b3d23, sa2, alpha + 1*2048, feat + 1*(BB*FEAT_SZ));

    convT2_kernel<false><<<dim3(16, BB), 512, SMEM_CT>>>(
        sa2, wsp + 16128, b3d23 + 16, sa1 /*unused*/, alpha + 2*2048, feat + 2*(BB*FEAT_SZ));

    relu_kernel<<<(3*BB*FEAT_SZ + 255)/256, 256>>>(feat, 3*BB*FEAT_SZ);

    conv45_kernel<<<BB, 512>>>(feat + 2*(BB*FEAT_SZ), w2d45, b2d45,
                               feat + 3*(BB*FEAT_SZ), feat + 4*(BB*FEAT_SZ));

    side_kernel<<<dim3(5, BB), 128>>>(x, feat, seg_w, seg_b, so_w, so_b,
                                      sp_wa, sp_ba, sp_wb, sp_bb, sp_sw, sp_sb,
                                      fuse, out);
}